// round 15
// baseline (speedup 1.0000x reference)
#include <cuda_runtime.h>
#include <cstdint>
#include <cstddef>

#define BB 128
#define TT 256
#define EMBD 200
#define NU1 400
#define NU2 200
#define KP1 (NU1 + 4)       // padded h1 row (floats) -> bulk-copyable
#define NU2P 204            // padded h2 row (floats)

// output layout: out2 | out1 | h2 | h1
#define OUT2_OFF 0
#define OUT1_OFF (BB*TT*NU2)
#define H2_OFF   (OUT1_OFF + BB*TT*NU1)
#define H1_OFF   (H2_OFF + BB*NU2)

__device__ float g_xn [(size_t)BB*TT*EMBD];
__device__ float g_xw1[(size_t)BB*TT*3*NU1];
__device__ float g_o1g[(size_t)TT*4*NU1*32];   // out1 [t][grp32][u][32b]
__device__ float g_o2t[(size_t)BB*TT*NU2];     // out2 [t][u][b]
__device__ float g_h1 [2*BB*KP1];              // padded rows
__device__ float g_h2 [2*BB*NU2P];             // padded rows
__device__ unsigned g_cnt1[4*32], g_gen1[4*32], g_gen1c[4*32], g_cnt2[4*32], g_gen2[4*32];

// ---- cp.async helpers ----
__device__ __forceinline__ void cp_async16(uint32_t s, const void* g)
{
    asm volatile("cp.async.cg.shared.global [%0], [%1], 16;" :: "r"(s), "l"(g));
}
__device__ __forceinline__ void cp_commit() { asm volatile("cp.async.commit_group;"); }
__device__ __forceinline__ void cp_wait0()  { asm volatile("cp.async.wait_all;"); }

// ---- mbarrier + bulk ----
__device__ __forceinline__ void mbar_init(uint32_t mbar)
{
    asm volatile("mbarrier.init.shared.b64 [%0], 1;" :: "r"(mbar) : "memory");
}
__device__ __forceinline__ void mbar_expect_tx(uint32_t mbar, uint32_t bytes)
{
    asm volatile("mbarrier.arrive.expect_tx.shared.b64 _, [%0], %1;"
                 :: "r"(mbar), "r"(bytes) : "memory");
}
__device__ __forceinline__ void mbar_wait(uint32_t mbar, uint32_t parity)
{
    uint32_t done;
    asm volatile(
        "{\n\t.reg .pred p;\n\t"
        "mbarrier.try_wait.parity.acquire.cta.shared::cta.b64 p, [%1], %2;\n\t"
        "selp.b32 %0, 1, 0, p;\n\t}"
        : "=r"(done) : "r"(mbar), "r"(parity) : "memory");
    if (!done) {
        asm volatile(
            "{\n\t.reg .pred P1;\n\t"
            "WAIT_LOOP_%=:\n\t"
            "mbarrier.try_wait.parity.acquire.cta.shared::cta.b64 P1, [%0], %1, 0x989680;\n\t"
            "@P1 bra.uni WAIT_DONE_%=;\n\t"
            "bra.uni WAIT_LOOP_%=;\n\t"
            "WAIT_DONE_%=:\n\t}"
            :: "r"(mbar), "r"(parity) : "memory");
    }
}
__device__ __forceinline__ void bulk_g2s(uint32_t dst, const void* src, uint32_t bytes,
                                         uint32_t mbar)
{
    asm volatile("cp.async.bulk.shared::cluster.global.mbarrier::complete_tx::bytes "
                 "[%0], [%1], %2, [%3];"
                 :: "r"(dst), "l"(src), "r"(bytes), "r"(mbar) : "memory");
}
__device__ __forceinline__ void fence_async()
{
    asm volatile("fence.proxy.async;" ::: "memory");
}

// packed f32x2 ops (sm_10x)
__device__ __forceinline__ unsigned long long fma2(unsigned long long a, unsigned long long b,
                                                   unsigned long long c)
{
    unsigned long long d;
    asm("fma.rn.f32x2 %0, %1, %2, %3;" : "=l"(d) : "l"(a), "l"(b), "l"(c));
    return d;
}
__device__ __forceinline__ unsigned long long add2(unsigned long long a, unsigned long long b)
{
    unsigned long long d;
    asm("add.rn.f32x2 %0, %1, %2;" : "=l"(d) : "l"(a), "l"(b));
    return d;
}
__device__ __forceinline__ unsigned long long pack2(float lo, float hi)
{
    unsigned long long d;
    asm("mov.b64 %0, {%1, %2};" : "=l"(d) : "f"(lo), "f"(hi));
    return d;
}
__device__ __forceinline__ float hsum2(unsigned long long a)
{
    float2 f = *reinterpret_cast<float2*>(&a);
    return f.x + f.y;
}
__device__ __forceinline__ float2 unpack2(unsigned long long a)
{
    return *reinterpret_cast<float2*>(&a);
}

// barrier primitives
__device__ __forceinline__ unsigned atom_arrive(unsigned* p)
{
    unsigned arr;
    asm volatile("atom.acq_rel.gpu.global.add.u32 %0, [%1], 1;"
                 : "=r"(arr) : "l"(p) : "memory");
    return arr;
}
__device__ __forceinline__ void st_release(unsigned* p, unsigned v)
{
    asm volatile("st.release.gpu.global.u32 [%0], %1;" :: "l"(p), "r"(v) : "memory");
}
__device__ __forceinline__ void st_relaxed(unsigned* p, unsigned v)
{
    asm volatile("st.relaxed.gpu.global.u32 [%0], %1;" :: "l"(p), "r"(v) : "memory");
}
__device__ __forceinline__ unsigned ld_acquire(const unsigned* p)
{
    unsigned v;
    asm volatile("ld.acquire.gpu.global.u32 %0, [%1];" : "=r"(v) : "l"(p) : "memory");
    return v;
}

__global__ void embed_bn(const int* __restrict__ tokens, const float* __restrict__ emb,
                         const float* __restrict__ gamma, const float* __restrict__ beta,
                         const float* __restrict__ mmean, const float* __restrict__ mvar)
{
    int idx = blockIdx.x * blockDim.x + threadIdx.x;
    if (idx >= BB*TT*EMBD) return;
    int d = idx % EMBD;
    int m = idx / EMBD;              // m = t*128 + b
    int b = m & (BB-1), t = m >> 7;
    int tok = tokens[b*TT + t];
    float s = gamma[d] * rsqrtf(mvar[d] + 1e-3f);
    g_xn[idx] = (emb[(size_t)tok*EMBD + d] - mmean[d]) * s + beta[d];
}

__global__ void init_state()
{
    int i = blockIdx.x * blockDim.x + threadIdx.x;
    if (i < 2*BB*KP1) g_h1[i] = 0.f;
    if (i < 2*BB*NU2P) g_h2[i] = 0.f;
    if (i < 4*32) {
        g_cnt1[i] = 0; g_gen1[i] = 0; g_gen1c[i] = 0; g_cnt2[i] = 0; g_gen2[i] = 0;
    }
}

__global__ void copy_h_strided(const float* __restrict__ src, float* __restrict__ dst,
                               int U, int KP)
{
    int i = blockIdx.x * blockDim.x + threadIdx.x;
    if (i < BB*U) dst[i] = src[(i/U)*KP + (i % U)];
}

// o1g [t][grp32][u][32] -> out1 [b][t][u];  grid (TT, 25, 4), block (32,8)
__global__ void transpose_o1(const float* __restrict__ src, float* __restrict__ dst)
{
    __shared__ float s[16][33];
    int t = blockIdx.x, u0 = blockIdx.y*16, g = blockIdx.z;
    int xi = threadIdx.x, yj = threadIdx.y;
    for (int r = yj; r < 16; r += 8)
        s[r][xi] = src[(((size_t)t*4 + g)*NU1 + u0 + r)*32 + xi];
    __syncthreads();
    for (int r = yj; r < 32; r += 8)
        if (xi < 16)
            dst[((size_t)(g*32 + r)*TT + t)*NU1 + u0 + xi] = s[xi][r];
}

// o2t [t][u][b] -> out2 [b][t][u]
__global__ void transpose_tub(const float* __restrict__ src, float* __restrict__ dst, int U)
{
    __shared__ float s[32][33];
    int t = blockIdx.x, u0 = blockIdx.y*32, b0 = blockIdx.z*32;
    int xi = threadIdx.x, yj = threadIdx.y;
    for (int i = yj; i < 32; i += 8) {
        int u = u0 + i;
        if (u < U) s[i][xi] = src[((size_t)t*U + u)*BB + b0 + xi];
    }
    __syncthreads();
    for (int i = yj; i < 32; i += 8) {
        int u = u0 + xi;
        if (u < U) dst[((size_t)(b0 + i)*TT + t)*U + u] = s[xi][i];
    }
}

// ---------------- SGEMM1: 128x128 tile, 8x8/thread, f32x2 (unchanged) ----------------
__global__ void __launch_bounds__(256, 2)
sgemm128(const float* __restrict__ A, const float* __restrict__ Bw,
         const float* __restrict__ bias, float* __restrict__ C, int N, int K)
{
    constexpr int AP = 132, BP = 132;
    __shared__ float As[2][8][AP];
    __shared__ float Bs[2][8][BP];
    const int tid = threadIdx.x;
    const int col0 = blockIdx.x * 128;
    const int row0 = blockIdx.y * 128;
    const int tx = tid & 15, ty = tid >> 4;

    for (int i = tid; i < 2*8*BP; i += 256) (&Bs[0][0][0])[i] = 0.f;
    __syncthreads();

    const int bkk = tid >> 5, bnq = (tid & 31) * 4;
    const int bgc = col0 + bnq;
    uint32_t bs_s0 = (uint32_t)__cvta_generic_to_shared(&Bs[0][bkk][bnq]);
    uint32_t bs_s1 = (uint32_t)__cvta_generic_to_shared(&Bs[1][bkk][bnq]);

    float4 rA;
    auto loadA = [&](int k0) {
        int m = tid >> 1, kq = (tid & 1) * 4;
        rA = *reinterpret_cast<const float4*>(A + (size_t)(row0 + m)*K + k0 + kq);
    };
    auto stsA = [&](int buf) {
        int m = tid >> 1, kq = (tid & 1) * 4;
        As[buf][kq+0][m] = rA.x; As[buf][kq+1][m] = rA.y;
        As[buf][kq+2][m] = rA.z; As[buf][kq+3][m] = rA.w;
    };
    auto asyncB = [&](int k0, int buf) {
        if (bgc < N)
            cp_async16(buf ? bs_s1 : bs_s0, Bw + (size_t)(k0 + bkk)*N + bgc);
    };

    loadA(0);
    asyncB(0, 0);
    cp_commit();

    unsigned long long acc[4][8] = {};
    const int NC = K / 8;
    for (int c = 0; c < NC; c++) {
        int buf = c & 1;
        cp_wait0();
        stsA(buf);
        __syncthreads();
        if (c + 1 < NC) {
            loadA((c+1)*8);
            asyncB((c+1)*8, buf ^ 1);
            cp_commit();
        }
#pragma unroll
        for (int kk = 0; kk < 8; kk++) {
            ulonglong2 a01 = *reinterpret_cast<const ulonglong2*>(&As[buf][kk][ty*8]);
            ulonglong2 a23 = *reinterpret_cast<const ulonglong2*>(&As[buf][kk][ty*8 + 4]);
            float4 b0 = *reinterpret_cast<const float4*>(&Bs[buf][kk][tx*4]);
            float4 b1 = *reinterpret_cast<const float4*>(&Bs[buf][kk][64 + tx*4]);
            unsigned long long ap[4] = {a01.x, a01.y, a23.x, a23.y};
            unsigned long long bd[8];
            bd[0] = pack2(b0.x, b0.x); bd[1] = pack2(b0.y, b0.y);
            bd[2] = pack2(b0.z, b0.z); bd[3] = pack2(b0.w, b0.w);
            bd[4] = pack2(b1.x, b1.x); bd[5] = pack2(b1.y, b1.y);
            bd[6] = pack2(b1.z, b1.z); bd[7] = pack2(b1.w, b1.w);
#pragma unroll
            for (int r = 0; r < 4; r++)
#pragma unroll
                for (int cc = 0; cc < 8; cc++)
                    acc[r][cc] = fma2(ap[r], bd[cc], acc[r][cc]);
        }
        __syncthreads();
    }

#pragma unroll
    for (int r = 0; r < 4; r++) {
        size_t gr = row0 + ty*8 + r*2;
#pragma unroll
        for (int cc = 0; cc < 8; cc++) {
            int gc = col0 + (cc < 4 ? tx*4 + cc : 64 + tx*4 + (cc - 4));
            if (gc < N) {
                float2 v = unpack2(acc[r][cc]);
                float bv = bias[gc];
                C[gr*N + gc]       = v.x + bv;
                C[(gr + 1)*N + gc] = v.y + bv;
            }
        }
    }
}

// ================= fused persistent kernel: L1 (100 CTAs) + L2 (40 CTAs) =================
// L1: CTA = 8 units x 64 batches, 2 batch-groups x 50 CTAs.
//     thread = 2 units x 3 gates x 2 batches (lane=batch, +32); K split across warp pairs.
//     h exchanged via ONE cp.async.bulk per step (h1p rows padded to KP1).
// L2: unchanged from R14 (bulk-staged on-the-fly projection + recurrence).
#define NTHR 320
#define L1_CTAS 100
#define FUSED_SMEM 224288

__global__ void __launch_bounds__(NTHR, 1)
fused_gru(const float* __restrict__ xw1, const float* __restrict__ Ur1,
          const float* __restrict__ br1, const float* __restrict__ W2,
          const float* __restrict__ Ur2, const float* __restrict__ b2full,
          const int* __restrict__ tokens,
          float* __restrict__ o1g, float* __restrict__ o2t,
          float* __restrict__ h1p, float* __restrict__ h2p)
{
    extern __shared__ float sm[];
    const int tid  = threadIdx.x;
    const int w    = tid >> 5;
    const int lane = tid & 31;

    if (blockIdx.x < L1_CTAS) {
        // ---------------- L1 role ----------------
        constexpr int UT = 8, KP = KP1, XS = 3*UT;   // XS = 24
        float*    sU    = sm;                        // [24][404]  (row = lu*3+g)
        float*    sH    = sU + 3*UT*KP;              // [64][404]  (bulk dst; offset 38784B, 128-aligned)
        float*    sX    = sH + 64*KP;                // [2][64][24]
        unsigned* sMask = (unsigned*)(sX + 2*64*XS); // [64][8]
        unsigned long long* sRed = (unsigned long long*)(sMask + 64*8); // [128][13]
        uint32_t  mbar  = (uint32_t)__cvta_generic_to_shared(sRed + 128*13);

        const int ub  = blockIdx.x % 50;
        const int g2  = blockIdx.x / 50;             // 64-batch group (0/1)
        const int u0  = ub * UT;
        const int b0  = g2 * 64;
        const int p   = w & 3;                       // unit-pair index
        const int half= w >> 2;                      // K half (warps 0-3 low, 4-7 high)
        const int uu0 = u0 + p*2;

        // one-time: U slice -> smem [lu*3+g][k]
        for (int i = tid; i < 3*UT*NU1; i += NTHR) {
            int k = i / (3*UT), c = i % (3*UT);
            int lu = c / 3, g = c % 3;
            sU[c*KP + k] = Ur1[(size_t)k*(3*NU1) + g*NU1 + u0 + lu];
        }
        // one-time: bit-packed mask for 64 batches
        for (int i = tid; i < 64*8; i += NTHR) {
            int bb = i >> 3, wd = i & 7;
            unsigned m = 0;
            for (int j = 0; j < 32; j++)
                m |= (tokens[(b0 + bb)*TT + wd*32 + j] != 0 ? 1u : 0u) << j;
            sMask[bb*8 + wd] = m;
        }
        // stage sX buffer 0 for t=0: [bb][g*8 + lu], 16B chunks
        const uint32_t sX_s = (uint32_t)__cvta_generic_to_shared(sX);
        for (int i = tid; i < 64*(XS/4); i += NTHR) {
            int bb = i / 6, qd = i % 6;
            int g = qd >> 1, l4 = (qd & 1) * 4;
            cp_async16(sX_s + (uint32_t)(bb*XS + g*UT + l4)*4,
                       xw1 + (size_t)(b0 + bb)*(3*NU1) + (size_t)g*NU1 + u0 + l4);
        }
        cp_commit();

        if (tid == 0) mbar_init(mbar);
        __syncthreads();
        const uint32_t sH_s = (uint32_t)__cvta_generic_to_shared(sH);
        if (tid == 0) {                       // kick off h(0) bulk (buf 0, zeroed, padded)
            mbar_expect_tx(mbar, (uint32_t)(64*KP*4));
            bulk_g2s(sH_s, h1p + (size_t)b0*KP, (uint32_t)(64*KP*4), mbar);
        }

        float bz[2], brr[2], bh[2];
#pragma unroll
        for (int j = 0; j < 2; j++) {
            bz[j]  = br1[uu0 + j];
            brr[j] = br1[NU1 + uu0 + j];
            bh[j]  = br1[2*NU1 + uu0 + j];
        }

        for (int t = 0; t < TT; t++) {
            float* hn = h1p + (size_t)((t + 1) & 1)*BB*KP;
            const float* sXc = sX + (t & 1)*64*XS;

            mbar_wait(mbar, (uint32_t)(t & 1));   // h(t) tile landed
            cp_wait0();                           // sX(t) landed
            __syncthreads();

            unsigned long long az[2][2] = {}, ar[2][2] = {}, ah[2][2] = {};
            if (w < 8) {
                const int kb = half * 200;
                const float* hrA = sH + lane*KP;
                const float* hrB = sH + (lane + 32)*KP;
#pragma unroll 2
                for (int k = kb; k < kb + 200; k += 4) {
                    ulonglong2 hA = *reinterpret_cast<const ulonglong2*>(hrA + k);
                    ulonglong2 hB = *reinterpret_cast<const ulonglong2*>(hrB + k);
#pragma unroll
                    for (int j = 0; j < 2; j++) {
                        const float* uc = sU + ((p*2 + j)*3)*KP + k;
                        ulonglong2 uz = *reinterpret_cast<const ulonglong2*>(uc);
                        ulonglong2 ur = *reinterpret_cast<const ulonglong2*>(uc + KP);
                        ulonglong2 uh = *reinterpret_cast<const ulonglong2*>(uc + 2*KP);
                        az[j][0] = fma2(hA.x, uz.x, az[j][0]); az[j][0] = fma2(hA.y, uz.y, az[j][0]);
                        az[j][1] = fma2(hB.x, uz.x, az[j][1]); az[j][1] = fma2(hB.y, uz.y, az[j][1]);
                        ar[j][0] = fma2(hA.x, ur.x, ar[j][0]); ar[j][0] = fma2(hA.y, ur.y, ar[j][0]);
                        ar[j][1] = fma2(hB.x, ur.x, ar[j][1]); ar[j][1] = fma2(hB.y, ur.y, ar[j][1]);
                        ah[j][0] = fma2(hA.x, uh.x, ah[j][0]); ah[j][0] = fma2(hA.y, uh.y, ah[j][0]);
                        ah[j][1] = fma2(hB.x, uh.x, ah[j][1]); ah[j][1] = fma2(hB.y, uh.y, ah[j][1]);
                    }
                }
            }
            __syncthreads();
            if (w >= 4 && w < 8) {                // upper K half -> smem
                unsigned long long* s = sRed + (size_t)((w - 4)*32 + lane)*13;
                s[0] = az[0][0]; s[1] = az[0][1]; s[2] = ar[0][0]; s[3] = ar[0][1];
                s[4] = ah[0][0]; s[5] = ah[0][1]; s[6] = az[1][0]; s[7] = az[1][1];
                s[8] = ar[1][0]; s[9] = ar[1][1]; s[10] = ah[1][0]; s[11] = ah[1][1];
            }
            __syncthreads();
            if (w < 4) {                          // reduce + epilogue
                const unsigned long long* s = sRed + (size_t)(w*32 + lane)*13;
                az[0][0] = add2(az[0][0], s[0]); az[0][1] = add2(az[0][1], s[1]);
                ar[0][0] = add2(ar[0][0], s[2]); ar[0][1] = add2(ar[0][1], s[3]);
                ah[0][0] = add2(ah[0][0], s[4]); ah[0][1] = add2(ah[0][1], s[5]);
                az[1][0] = add2(az[1][0], s[6]); az[1][1] = add2(az[1][1], s[7]);
                ar[1][0] = add2(ar[1][0], s[8]); ar[1][1] = add2(ar[1][1], s[9]);
                ah[1][0] = add2(ah[1][0], s[10]); ah[1][1] = add2(ah[1][1], s[11]);
#pragma unroll
                for (int q = 0; q < 2; q++) {
                    int bb = lane + q*32;
                    const int mk = (sMask[bb*8 + (t >> 5)] >> (t & 31)) & 1;
                    float hv[2];
#pragma unroll
                    for (int j = 0; j < 2; j++) {
                        float vz = hsum2(az[j][q]) + bz[j];
                        float vr = hsum2(ar[j][q]) + brr[j];
                        float vh = hsum2(ah[j][q]) + bh[j];
                        int lu = p*2 + j;
                        float xz = sXc[bb*XS + lu];
                        float xr = sXc[bb*XS + UT + lu];
                        float xh = sXc[bb*XS + 2*UT + lu];
                        float z  = 1.f / (1.f + __expf(-(xz + vz)));
                        float r  = 1.f / (1.f + __expf(-(xr + vr)));
                        float hh = tanhf(xh + r * vh);
                        float hold = sH[bb*KP + uu0 + j];
                        float hnew = z*hold + (1.f - z)*hh;
                        hv[j] = mk ? hnew : hold;
                    }
                    *reinterpret_cast<float2*>(hn + (size_t)(b0 + bb)*KP + uu0)
                        = make_float2(hv[0], hv[1]);
                    size_t ob = (((size_t)t*4 + g2*2 + q)*NU1 + uu0)*32 + lane;
                    o1g[ob]      = hv[0];
                    o1g[ob + 32] = hv[1];
                }
            }

            // prefetch sX(t+1)
            if (t + 1 < TT) {
                uint32_t dst = sX_s + (uint32_t)(((t+1) & 1)*64*XS)*4;
                for (int i = tid; i < 64*(XS/4); i += NTHR) {
                    int bb = i / 6, qd = i % 6;
                    int g = qd >> 1, l4 = (qd & 1) * 4;
                    cp_async16(dst + (uint32_t)(bb*XS + g*UT + l4)*4,
                               xw1 + ((size_t)(t+1)*BB + b0 + bb)*(size_t)(3*NU1)
                                   + (size_t)g*NU1 + u0 + l4);
                }
                cp_commit();
            }

            // group barrier (50 CTAs of this 64-batch group), tid0-only protocol
            __syncthreads();
            if (tid == 0) {
                unsigned target = (unsigned)(t + 1);
                unsigned arr = atom_arrive(g_cnt1 + g2*32);
                if (arr == 49u) {
                    st_relaxed(g_cnt1 + g2*32, 0);
                    st_release(g_gen1  + g2*32, target);
                    st_release(g_gen1c + g2*32, target);
                } else {
                    while (ld_acquire(g_gen1 + g2*32) < target) { }
                }
                if (t + 1 < TT) {                 // h(t+1) complete group-wide
                    fence_async();
                    mbar_expect_tx(mbar, (uint32_t)(64*KP*4));
                    bulk_g2s(sH_s, h1p + (size_t)(((t+1) & 1)*BB + b0)*KP,
                             (uint32_t)(64*KP*4), mbar);
                }
            }
            // other threads proceed to next iteration's mbar_wait
        }
    } else {
        // ---------------- L2 role (R14-identical; gen1c maps 4 groups -> 2) ----------------
        constexpr int UT2 = 20, COLS = 3*UT2;
        constexpr int KW1 = NU1 + 4;
        float* sW2 = sm;                             // [60][404]
        float* sU2 = sW2 + COLS*KW1;                 // [60][204]
        float* sO1 = sU2 + COLS*NU2P;                // [400][32]
        float* sH2 = sO1 + NU1*32;                   // [32][204]
        unsigned* sMask = (unsigned*)(sH2 + 32*NU2P);// [32][8]
        uint32_t  mbar  = (uint32_t)__cvta_generic_to_shared(sMask + 32*8);

        const int ci  = blockIdx.x - L1_CTAS;
        const int u20 = (ci % 10) * UT2;
        const int grp = ci / 10;                     // 32-batch group (0..3)
        const int b0  = grp * 32;
        const int b   = b0 + lane;

        for (int i = tid; i < COLS*NU1; i += NTHR) {
            int k = i / COLS, c = i % COLS;
            int ul = c / 3, g = c % 3;
            sW2[c*KW1 + k] = W2[(size_t)k*(3*NU2) + g*NU2 + u20 + ul];
        }
        for (int i = tid; i < COLS*NU2; i += NTHR) {
            int k = i / COLS, c = i % COLS;
            int ul = c / 3, g = c % 3;
            sU2[c*NU2P + k] = Ur2[(size_t)k*(3*NU2) + g*NU2 + u20 + ul];
        }
        for (int i = tid; i < 32*8; i += NTHR) {
            int bb = i >> 3, wd = i & 7;
            unsigned m = 0;
            for (int j = 0; j < 32; j++)
                m |= (tokens[(b0 + bb)*TT + wd*32 + j] != 0 ? 1u : 0u) << j;
            sMask[bb*8 + wd] = m;
        }

        float bi[6], brc[6];
#pragma unroll
        for (int j = 0; j < 6; j++) {
            int c = w*6 + j;
            int ul = c / 3, g = c % 3;
            bi[j]  = b2full[g*NU2 + u20 + ul];
            brc[j] = b2full[3*NU2 + g*NU2 + u20 + ul];
        }

        const uint32_t sO1_s = (uint32_t)__cvta_generic_to_shared(sO1);
        const uint32_t sH2_s = (uint32_t)__cvta_generic_to_shared(sH2);
        const float* h2row = sH2 + lane*NU2P;

        if (tid == 0) mbar_init(mbar);
        __syncthreads();

        for (int t = 0; t < TT; t++) {
            const float* hg = h2p + (t & 1) * (BB*NU2P);
            float*       hn = h2p + ((t + 1) & 1) * (BB*NU2P);

            if (tid == 0) {
                unsigned need = (unsigned)(t + 1);
                while (ld_acquire(g_gen1c + (grp >> 1)*32) < need) { }
                mbar_expect_tx(mbar, (uint32_t)(NU1*32*4 + 32*NU2P*4));
                bulk_g2s(sO1_s, o1g + ((size_t)t*4 + grp)*NU1*32, NU1*32*4, mbar);
                bulk_g2s(sH2_s, hg + (size_t)b0*NU2P, 32*NU2P*4, mbar);
            }
            mbar_wait(mbar, (uint32_t)(t & 1));

            unsigned long long accP[6] = {}, accR[6] = {};
#pragma unroll 2
            for (int k = 0; k < NU1; k += 4) {
                float o0 = sO1[(k+0)*32 + lane];
                float o1 = sO1[(k+1)*32 + lane];
                float o2 = sO1[(k+2)*32 + lane];
                float o3 = sO1[(k+3)*32 + lane];
                unsigned long long p01 = pack2(o0, o1), p23 = pack2(o2, o3);
#pragma unroll
                for (int j = 0; j < 6; j++) {
                    const float* wp = sW2 + (w*6 + j)*KW1 + k;
                    ulonglong2 wv = *reinterpret_cast<const ulonglong2*>(wp);
                    accP[j] = fma2(p01, wv.x, accP[j]);
                    accP[j] = fma2(p23, wv.y, accP[j]);
                }
            }
#pragma unroll 2
            for (int k = 0; k < NU2; k += 4) {
                ulonglong2 h2v = *reinterpret_cast<const ulonglong2*>(h2row + k);
#pragma unroll
                for (int j = 0; j < 6; j++) {
                    const float* up = sU2 + (w*6 + j)*NU2P + k;
                    ulonglong2 uv = *reinterpret_cast<const ulonglong2*>(up);
                    accR[j] = fma2(h2v.x, uv.x, accR[j]);
                    accR[j] = fma2(h2v.y, uv.y, accR[j]);
                }
            }

            const int mk = (sMask[lane*8 + (t >> 5)] >> (t & 31)) & 1;
#pragma unroll
            for (int je = 0; je < 2; je++) {
                int ug = u20 + 2*w + je;
                float Pz = hsum2(accP[je*3+0]) + bi[je*3+0];
                float Pr = hsum2(accP[je*3+1]) + bi[je*3+1];
                float Ph = hsum2(accP[je*3+2]) + bi[je*3+2];
                float Rz = hsum2(accR[je*3+0]) + brc[je*3+0];
                float Rr = hsum2(accR[je*3+1]) + brc[je*3+1];
                float Rh = hsum2(accR[je*3+2]) + brc[je*3+2];
                float z  = 1.f / (1.f + __expf(-(Pz + Rz)));
                float r  = 1.f / (1.f + __expf(-(Pr + Rr)));
                float hh = tanhf(Ph + r * Rh);
                float hold = h2row[ug];
                float hnew = z*hold + (1.f - z)*hh;
                float hv = mk ? hnew : hold;
                hn[(size_t)b*NU2P + ug] = hv;
                o2t[((size_t)t*NU2 + ug)*BB + b] = hv;
            }

            __syncthreads();
            if (tid == 0) {
                unsigned target = (unsigned)(t + 1);
                unsigned arr = atom_arrive(g_cnt2 + grp*32);
                if (arr == 9u) {
                    st_relaxed(g_cnt2 + grp*32, 0);
                    st_release(g_gen2 + grp*32, target);
                } else {
                    while (ld_acquire(g_gen2 + grp*32) < target) { }
                }
            }
            __syncthreads();
        }
    }
}

extern "C" void kernel_launch(void* const* d_in, const int* in_sizes, int n_in,
                              void* d_out, int out_size)
{
    const int*   tokens = (const int*)  d_in[0];
    const float* emb    = (const float*)d_in[1];
    const float* gamma  = (const float*)d_in[2];
    const float* beta   = (const float*)d_in[3];
    const float* mmean  = (const float*)d_in[4];
    const float* mvar   = (const float*)d_in[5];
    const float* W1     = (const float*)d_in[6];
    const float* Ur1    = (const float*)d_in[7];
    const float* b1     = (const float*)d_in[8];
    const float* W2     = (const float*)d_in[9];
    const float* Ur2    = (const float*)d_in[10];
    const float* b2     = (const float*)d_in[11];

    float* out  = (float*)d_out;
    float* out2 = out + OUT2_OFF;
    float* out1 = out + OUT1_OFF;
    float* h2o  = out + H2_OFF;
    float* h1o  = out + H1_OFF;

    void *p_xn, *p_xw1, *p_o1g, *p_o2t, *p_h1, *p_h2;
    cudaGetSymbolAddress(&p_xn,  g_xn);
    cudaGetSymbolAddress(&p_xw1, g_xw1);
    cudaGetSymbolAddress(&p_o1g, g_o1g);
    cudaGetSymbolAddress(&p_o2t, g_o2t);
    cudaGetSymbolAddress(&p_h1,  g_h1);
    cudaGetSymbolAddress(&p_h2,  g_h2);
    float* xn  = (float*)p_xn;
    float* xw1 = (float*)p_xw1;
    float* o1g = (float*)p_o1g;
    float* o2t = (float*)p_o2t;
    float* h1p = (float*)p_h1;
    float* h2p = (float*)p_h2;

    cudaFuncSetAttribute(fused_gru, cudaFuncAttributeMaxDynamicSharedMemorySize, FUSED_SMEM);

    embed_bn<<<(BB*TT*EMBD + 255)/256, 256>>>(tokens, emb, gamma, beta, mmean, mvar);
    init_state<<<(2*BB*KP1 + 255)/256, 256>>>();

    // xw1 = xn @ W1 + b1[0]
    sgemm128<<<dim3((3*NU1 + 127)/128, (BB*TT)/128), 256>>>(xn, W1, b1, xw1, 3*NU1, EMBD);

    // fused persistent L1+L2
    fused_gru<<<140, NTHR, FUSED_SMEM>>>(xw1, Ur1, b1 + 3*NU1, W2, Ur2, b2,
                                         tokens, o1g, o2t, h1p, h2p);

    copy_h_strided<<<(BB*NU1 + 255)/256, 256>>>(h1p, h1o, NU1, KP1);   // T even -> buf 0
    copy_h_strided<<<(BB*NU2 + 255)/256, 256>>>(h2p, h2o, NU2, NU2P);
    transpose_o1<<<dim3(TT, 25, 4), dim3(32, 8)>>>(o1g, out1);
    transpose_tub<<<dim3(TT, (NU2 + 31)/32, BB/32), dim3(32, 8)>>>(o2t, out2, NU2);
}